// round 2
// baseline (speedup 1.0000x reference)
#include <cuda_runtime.h>
#include <cstdint>

#define M_PTS 300000
#define C_DIM 128
#define S_NUM 4
#define HASH_SIZE (1u << 20)
#define HASH_MASK (HASH_SIZE - 1u)

// ---------------- scratch (static device globals; no allocation) ----------------
__device__ unsigned int g_hash_keys[HASH_SIZE];
__device__ int          g_hash_vals[HASH_SIZE];
__device__ int          g_num_buckets;
__device__ int          g_point_bucket[M_PTS];
__device__ int          g_bucket_count[M_PTS];
__device__ float        g_bucket_sums[(size_t)M_PTS * C_DIM];   // 153.6 MB
__device__ float        g_ch_sum[S_NUM * C_DIM];
__device__ float        g_ch_sumsq[S_NUM * C_DIM];
__device__ float        g_bn_scale[S_NUM * C_DIM];
__device__ float        g_bn_shift[S_NUM * C_DIM];

// ---------------- small helpers ----------------
__device__ __forceinline__ unsigned long long pack2(float a) {
    unsigned long long r;
    unsigned int u = __float_as_uint(a);
    asm("mov.b64 %0, {%1, %1};" : "=l"(r) : "r"(u));
    return r;
}
__device__ __forceinline__ void ffma2(unsigned long long& d,
                                      unsigned long long a,
                                      unsigned long long b) {
    // packed 2-wide fp32 FMA (sm_103a): d.lo = a.lo*b.lo + d.lo ; d.hi likewise
    asm("fma.rn.f32x2 %0, %1, %2, %0;" : "+l"(d) : "l"(a), "l"(b));
}

// ---------------- clears ----------------
__global__ void clear_stats_kernel() {
    int i = threadIdx.x;
    if (i < S_NUM * C_DIM) { g_ch_sum[i] = 0.f; g_ch_sumsq[i] = 0.f; }
}

// Clears only the prefix of bucket arrays that the PREVIOUS scale (or previous
// graph replay) dirtied; g_num_buckets still holds that count when this runs.
__global__ void clear_used_kernel() {
    int prev = g_num_buckets;
    int i = blockIdx.x * blockDim.x + threadIdx.x;
    int n4 = prev * (C_DIM / 4);
    if (i < n4) ((float4*)g_bucket_sums)[i] = make_float4(0.f, 0.f, 0.f, 0.f);
    if (i < prev) g_bucket_count[i] = 0;
}

__global__ void clear_hash_kernel() {
    unsigned int i = blockIdx.x * blockDim.x + threadIdx.x;
    if (i < HASH_SIZE) { g_hash_keys[i] = 0xFFFFFFFFu; g_hash_vals[i] = -1; }
    if (i == 0) g_num_buckets = 0;
}

// ---------------- bucket assignment (hash insert) ----------------
__global__ void assign_kernel(const int* __restrict__ indices, int shift) {
    int p = blockIdx.x * blockDim.x + threadIdx.x;
    if (p >= M_PTS) return;
    int4 v = ((const int4*)indices)[p];               // batch, x, y, z
    unsigned int cx = ((unsigned int)v.y) >> shift;
    unsigned int cy = ((unsigned int)v.z) >> shift;
    unsigned int cz = ((unsigned int)v.w) >> shift;
    unsigned int key = (((unsigned int)v.x * 512u + cx) * 512u + cy) * 512u + cz;

    unsigned int slot = (key * 2654435761u) & HASH_MASK;
    int id;
    while (true) {
        unsigned int prev = atomicCAS(&g_hash_keys[slot], 0xFFFFFFFFu, key);
        if (prev == 0xFFFFFFFFu) {
            id = atomicAdd(&g_num_buckets, 1);
            atomicExch(&g_hash_vals[slot], id);       // publish
            break;
        } else if (prev == key) {
            do { id = atomicAdd(&g_hash_vals[slot], 0); } while (id < 0);
            break;
        }
        slot = (slot + 1u) & HASH_MASK;
    }
    g_point_bucket[p] = id;
    atomicAdd(&g_bucket_count[id], 1);
}

// ---------------- scatter-add feats into bucket sums ----------------
__global__ void accumulate_kernel(const float* __restrict__ feats) {
    int t = blockIdx.x * blockDim.x + threadIdx.x;
    if (t >= M_PTS * 32) return;                       // 32 float4 groups per point
    int p = t >> 5;
    int cg = t & 31;
    int b = __ldg(&g_point_bucket[p]);
    float4 f = ((const float4*)feats)[t];
    float* dst = &g_bucket_sums[(size_t)b * C_DIM + cg * 4];
    atomicAdd(dst + 0, f.x);
    atomicAdd(dst + 1, f.y);
    atomicAdd(dst + 2, f.z);
    atomicAdd(dst + 3, f.w);
}

// ---------------- fused Os-build + GEMM + BN-stat epilogue ----------------
// Block: 128 rows x 128 cols, 256 threads, each thread 8x8 outputs (as f32x2 pairs).
__global__ void __launch_bounds__(256, 1)
gemm_kernel(const float* __restrict__ feats, const float* __restrict__ W,
            const float* __restrict__ bias, float* __restrict__ out, int si) {
    extern __shared__ float smf[];
    float* As = smf;                   // [128][132] Os tile (padded)
    float* Bs = smf + 128 * 132;       // [128][128] W tile (row k, col c)
    __shared__ float s_sum[128];
    __shared__ float s_sq[128];

    int tid = threadIdx.x;
    if (tid < 128) { s_sum[tid] = 0.f; s_sq[tid] = 0.f; }

    int row0 = blockIdx.x * 128;
    int rows = M_PTS - row0; if (rows > 128) rows = 128;

    // load W[si]
    const float4* W4 = (const float4*)(W + (size_t)si * C_DIM * C_DIM);
    #pragma unroll
    for (int i = 0; i < 16; i++)
        ((float4*)Bs)[i * 256 + tid] = W4[i * 256 + tid];

    // build Os tile: (feats - bucket_mean) * feats
    const float4* f4 = (const float4*)feats;
    const float4* s4 = (const float4*)g_bucket_sums;
    #pragma unroll
    for (int i = 0; i < 16; i++) {
        int lin = i * 256 + tid;
        int rl = lin >> 5;
        int cg = lin & 31;
        float4 os = make_float4(0.f, 0.f, 0.f, 0.f);
        if (rl < rows) {
            int p = row0 + rl;
            int b = __ldg(&g_point_bucket[p]);
            float inv = 1.0f / (float)__ldg(&g_bucket_count[b]);
            float4 f = f4[(size_t)p * 32 + cg];
            float4 su = s4[(size_t)b * 32 + cg];
            os.x = (f.x - su.x * inv) * f.x;
            os.y = (f.y - su.y * inv) * f.y;
            os.z = (f.z - su.z * inv) * f.z;
            os.w = (f.w - su.w * inv) * f.w;
        }
        *(float4*)&As[rl * 132 + cg * 4] = os;
    }
    __syncthreads();

    int r0 = (tid >> 4) * 8;
    int c0 = (tid & 15) * 8;

    unsigned long long acc[8][4];
    #pragma unroll
    for (int i = 0; i < 8; i++)
        #pragma unroll
        for (int j = 0; j < 4; j++) acc[i][j] = 0ull;

    const float* Asr = As + r0 * 132;
    #pragma unroll 8
    for (int k = 0; k < 128; k++) {
        ulonglong2 b01 = *(const ulonglong2*)&Bs[k * 128 + c0];
        ulonglong2 b23 = *(const ulonglong2*)&Bs[k * 128 + c0 + 4];
        #pragma unroll
        for (int i = 0; i < 8; i++) {
            unsigned long long aa = pack2(Asr[i * 132 + k]);
            ffma2(acc[i][0], aa, b01.x);
            ffma2(acc[i][1], aa, b01.y);
            ffma2(acc[i][2], aa, b23.x);
            ffma2(acc[i][3], aa, b23.y);
        }
    }

    // epilogue: bias add, write h, per-channel partial sums for BN
    const float* bp = bias + si * C_DIM + c0;
    float bl[8];
    #pragma unroll
    for (int j = 0; j < 8; j++) bl[j] = __ldg(&bp[j]);

    float csum[8], csq[8];
    #pragma unroll
    for (int j = 0; j < 8; j++) { csum[j] = 0.f; csq[j] = 0.f; }

    float* outp = out + (size_t)row0 * (S_NUM * C_DIM) + si * C_DIM + c0;
    #pragma unroll
    for (int i = 0; i < 8; i++) {
        if (r0 + i < rows) {
            float h[8];
            #pragma unroll
            for (int j = 0; j < 4; j++) {
                unsigned long long v = acc[i][j];
                h[2 * j]     = __uint_as_float((unsigned int)v) + bl[2 * j];
                h[2 * j + 1] = __uint_as_float((unsigned int)(v >> 32)) + bl[2 * j + 1];
            }
            *(float4*)&outp[(size_t)(r0 + i) * (S_NUM * C_DIM)] =
                make_float4(h[0], h[1], h[2], h[3]);
            *(float4*)&outp[(size_t)(r0 + i) * (S_NUM * C_DIM) + 4] =
                make_float4(h[4], h[5], h[6], h[7]);
            #pragma unroll
            for (int j = 0; j < 8; j++) { csum[j] += h[j]; csq[j] += h[j] * h[j]; }
        }
    }
    #pragma unroll
    for (int j = 0; j < 8; j++) {
        atomicAdd(&s_sum[c0 + j], csum[j]);
        atomicAdd(&s_sq[c0 + j], csq[j]);
    }
    __syncthreads();
    if (tid < 128) {
        atomicAdd(&g_ch_sum[si * C_DIM + tid], s_sum[tid]);
        atomicAdd(&g_ch_sumsq[si * C_DIM + tid], s_sq[tid]);
    }
}

// ---------------- BN finalize: per (scale, channel) affine ----------------
__global__ void finalize_kernel(const float* __restrict__ gamma,
                                const float* __restrict__ beta) {
    int i = blockIdx.x * blockDim.x + threadIdx.x;
    if (i >= S_NUM * C_DIM) return;
    const float invM = 1.0f / (float)M_PTS;
    float mu  = g_ch_sum[i] * invM;
    float var = g_ch_sumsq[i] * invM - mu * mu;
    float rstd = rsqrtf(var + 1e-5f);
    float a = rstd * __ldg(&gamma[i]);
    g_bn_scale[i] = a;
    g_bn_shift[i] = __ldg(&beta[i]) - mu * a;
}

// ---------------- BN apply + LeakyReLU over whole output ----------------
__global__ void bn_apply_kernel(float* __restrict__ out) {
    long long i = (long long)blockIdx.x * blockDim.x + threadIdx.x;
    if (i >= (long long)M_PTS * 128) return;           // float4 granularity
    int sc4 = (int)(i & 127);                           // float4 index into [512]
    float4 h = ((float4*)out)[i];
    float4 a = ((const float4*)g_bn_scale)[sc4];
    float4 b = ((const float4*)g_bn_shift)[sc4];
    float x0 = h.x * a.x + b.x;
    float x1 = h.y * a.y + b.y;
    float x2 = h.z * a.z + b.z;
    float x3 = h.w * a.w + b.w;
    x0 = x0 > 0.f ? x0 : 0.01f * x0;
    x1 = x1 > 0.f ? x1 : 0.01f * x1;
    x2 = x2 > 0.f ? x2 : 0.01f * x2;
    x3 = x3 > 0.f ? x3 : 0.01f * x3;
    ((float4*)out)[i] = make_float4(x0, x1, x2, x3);
}

// ---------------- launch ----------------
extern "C" void kernel_launch(void* const* d_in, const int* in_sizes, int n_in,
                              void* d_out, int out_size) {
    const float* feats   = (const float*)d_in[0];
    const int*   indices = (const int*)d_in[1];
    const float* W       = (const float*)d_in[2];
    const float* b       = (const float*)d_in[3];
    const float* gamma   = (const float*)d_in[4];
    const float* beta    = (const float*)d_in[5];
    float* out = (float*)d_out;

    const int smem = (128 * 132 + 128 * 128) * 4;      // 133120 B
    cudaFuncSetAttribute(gemm_kernel,
                         cudaFuncAttributeMaxDynamicSharedMemorySize, smem);

    clear_stats_kernel<<<1, 512>>>();

    const int shifts[S_NUM] = {1, 2, 3, 4};            // scales 2,4,8,16
    for (int si = 0; si < S_NUM; si++) {
        clear_used_kernel<<<(M_PTS * 32 + 255) / 256, 256>>>();
        clear_hash_kernel<<<(int)((HASH_SIZE + 255) / 256), 256>>>();
        assign_kernel<<<(M_PTS + 255) / 256, 256>>>(indices, shifts[si]);
        accumulate_kernel<<<(M_PTS * 32 + 255) / 256, 256>>>(feats);
        gemm_kernel<<<(M_PTS + 127) / 128, 256, smem>>>(feats, W, b, out, si);
    }
    finalize_kernel<<<1, 512>>>(gamma, beta);
    bn_apply_kernel<<<(int)(((long long)M_PTS * 128 + 255) / 256), 256>>>(out);
}

// round 6
// speedup vs baseline: 1.1754x; 1.1754x over previous
#include <cuda_runtime.h>
#include <cuda_bf16.h>
#include <cstdint>

#define M_PTS 300000
#define C_DIM 128
#define S_NUM 4
#define HASH_SIZE (1u << 20)
#define HASH_MASK (HASH_SIZE - 1u)

#define PA 136   // A-tile pitch in bf16 elements (128 + 8 pad)
#define PB 138   // B-tile pitch in bf16 elements (128 + 10 pad)

typedef unsigned long long ull_t;

// ---------------- scratch (static device globals; no allocation) ----------------
__device__ unsigned int g_hash_keys[HASH_SIZE];
__device__ int          g_hash_vals[HASH_SIZE];
__device__ int          g_num_buckets;
__device__ int          g_point_bucket[M_PTS];
__device__ int          g_bucket_count[M_PTS];
__device__ float        g_bucket_sums[(size_t)M_PTS * C_DIM];   // 153.6 MB
__device__ float        g_ch_sum[S_NUM * C_DIM];
__device__ float        g_ch_sumsq[S_NUM * C_DIM];
__device__ float        g_bn_scale[S_NUM * C_DIM];
__device__ float        g_bn_shift[S_NUM * C_DIM];
// prepped W tiles: [si][n][PB] bf16, hi and lo parts (transposed: W[k][n] -> B[n][k])
__device__ __align__(16) unsigned short g_Whi[S_NUM * C_DIM * PB];
__device__ __align__(16) unsigned short g_Wlo[S_NUM * C_DIM * PB];

// ---------------- clears ----------------
__global__ void clear_stats_kernel() {
    int i = threadIdx.x;
    if (i < S_NUM * C_DIM) { g_ch_sum[i] = 0.f; g_ch_sumsq[i] = 0.f; }
}

// Clears only the prefix of bucket arrays that the PREVIOUS scale (or previous
// graph replay) dirtied; g_num_buckets still holds that count when this runs.
__global__ void clear_used_kernel() {
    int prev = g_num_buckets;
    int i = blockIdx.x * blockDim.x + threadIdx.x;
    int n4 = prev * (C_DIM / 4);
    if (i < n4) ((float4*)g_bucket_sums)[i] = make_float4(0.f, 0.f, 0.f, 0.f);
    if (i < prev) g_bucket_count[i] = 0;
}

__global__ void clear_hash_kernel() {
    unsigned int i = blockIdx.x * blockDim.x + threadIdx.x;
    if (i < HASH_SIZE) { g_hash_keys[i] = 0xFFFFFFFFu; g_hash_vals[i] = -1; }
    if (i == 0) g_num_buckets = 0;
}

// ---------------- W prep: transpose + bf16 hi/lo split, once per scale ----------------
__global__ void prep_w_kernel(const float* __restrict__ W) {
    int si = blockIdx.x;
    for (int it = threadIdx.x; it < C_DIM * PB; it += blockDim.x) {
        int n = it / PB;
        int k = it - n * PB;
        unsigned short hi = 0, lo = 0;
        if (k < C_DIM) {
            float v = __ldg(&W[((size_t)si * C_DIM + k) * C_DIM + n]);
            __nv_bfloat16 h = __float2bfloat16_rn(v);
            float l = v - __bfloat162float(h);
            hi = __bfloat16_as_ushort(h);
            lo = __bfloat16_as_ushort(__float2bfloat16_rn(l));
        }
        g_Whi[si * C_DIM * PB + it] = hi;
        g_Wlo[si * C_DIM * PB + it] = lo;
    }
}

// ---------------- bucket assignment (hash insert) ----------------
__global__ void assign_kernel(const int* __restrict__ indices, int shift) {
    int p = blockIdx.x * blockDim.x + threadIdx.x;
    if (p >= M_PTS) return;
    int4 v = ((const int4*)indices)[p];               // batch, x, y, z
    unsigned int cx = ((unsigned int)v.y) >> shift;
    unsigned int cy = ((unsigned int)v.z) >> shift;
    unsigned int cz = ((unsigned int)v.w) >> shift;
    unsigned int key = (((unsigned int)v.x * 512u + cx) * 512u + cy) * 512u + cz;

    unsigned int slot = (key * 2654435761u) & HASH_MASK;
    int id;
    while (true) {
        unsigned int prev = atomicCAS(&g_hash_keys[slot], 0xFFFFFFFFu, key);
        if (prev == 0xFFFFFFFFu) {
            id = atomicAdd(&g_num_buckets, 1);
            atomicExch(&g_hash_vals[slot], id);       // publish
            break;
        } else if (prev == key) {
            do { id = atomicAdd(&g_hash_vals[slot], 0); } while (id < 0);
            break;
        }
        slot = (slot + 1u) & HASH_MASK;
    }
    g_point_bucket[p] = id;
    atomicAdd(&g_bucket_count[id], 1);
}

// ---------------- scatter-add feats into bucket sums ----------------
__global__ void accumulate_kernel(const float* __restrict__ feats) {
    int t = blockIdx.x * blockDim.x + threadIdx.x;
    if (t >= M_PTS * 32) return;                       // 32 float4 groups per point
    int p = t >> 5;
    int cg = t & 31;
    int b = __ldg(&g_point_bucket[p]);
    float4 f = ((const float4*)feats)[t];
    float* dst = &g_bucket_sums[(size_t)b * C_DIM + cg * 4];
    atomicAdd(dst + 0, f.x);
    atomicAdd(dst + 1, f.y);
    atomicAdd(dst + 2, f.z);
    atomicAdd(dst + 3, f.w);
}

// ---------------- HMMA GEMM: Os build + 3x bf16-split mma.sync + BN-stat epilogue ----
__device__ __forceinline__ void mma16816(float* c, const uint32_t* a,
                                         uint32_t b0, uint32_t b1) {
    asm volatile(
        "mma.sync.aligned.m16n8k16.row.col.f32.bf16.bf16.f32 "
        "{%0,%1,%2,%3}, {%4,%5,%6,%7}, {%8,%9}, {%0,%1,%2,%3};"
        : "+f"(c[0]), "+f"(c[1]), "+f"(c[2]), "+f"(c[3])
        : "r"(a[0]), "r"(a[1]), "r"(a[2]), "r"(a[3]), "r"(b0), "r"(b1));
}

__global__ void __launch_bounds__(256, 1)
gemm_tc_kernel(const float* __restrict__ feats, const float* __restrict__ bias,
               float* __restrict__ out, int si)
{
    extern __shared__ __align__(16) char smraw[];
    unsigned short* Ah = (unsigned short*)smraw;        // [128][PA]
    unsigned short* Al = Ah + 128 * PA;
    unsigned short* Bh = Al + 128 * PA;                 // [128][PB]
    unsigned short* Bl = Bh + 128 * PB;

    __shared__ float s_sum[128];
    __shared__ float s_sq[128];
    __shared__ float s_bias[128];
    __shared__ float s_inv[128];
    __shared__ int   s_bkt[128];

    int tid = threadIdx.x;
    int wid = tid >> 5;
    int lid = tid & 31;

    int row0 = blockIdx.x * 128;
    int rows = M_PTS - row0; if (rows > 128) rows = 128;

    if (tid < 128) {
        s_sum[tid] = 0.f; s_sq[tid] = 0.f;
        s_bias[tid] = __ldg(&bias[si * C_DIM + tid]);
        int b = 0; float inv = 0.f;
        if (tid < rows) {
            b = __ldg(&g_point_bucket[row0 + tid]);
            inv = 1.0f / (float)__ldg(&g_bucket_count[b]);
        }
        s_bkt[tid] = b; s_inv[tid] = inv;
    }
    __syncthreads();

    // --- B tiles: flat vectorized copy of prepped W (already transposed + split) ---
    {
        const uint4* srcH = (const uint4*)(g_Whi + (size_t)si * C_DIM * PB);
        const uint4* srcL = (const uint4*)(g_Wlo + (size_t)si * C_DIM * PB);
        uint4* dH = (uint4*)Bh;
        uint4* dL = (uint4*)Bl;
        const int nvec = C_DIM * PB * 2 / 16;          // 2208
        for (int it = tid; it < nvec; it += 256) {
            dH[it] = srcH[it];
            dL[it] = srcL[it];
        }
    }

    // --- A tile: Os = (f - mean)*f, split bf16 hi/lo ---
    {
        const float4* f4 = (const float4*)feats;
        const float4* s4 = (const float4*)g_bucket_sums;
        for (int it = tid; it < 4096; it += 256) {
            int r = it >> 5, cg = it & 31;
            ull_t hv = 0ull, lv = 0ull;
            if (r < rows) {
                int p = row0 + r;
                float4 f = f4[(size_t)p * 32 + cg];
                float4 su = s4[(size_t)s_bkt[r] * 32 + cg];
                float inv = s_inv[r];
                float o0 = (f.x - su.x * inv) * f.x;
                float o1 = (f.y - su.y * inv) * f.y;
                float o2 = (f.z - su.z * inv) * f.z;
                float o3 = (f.w - su.w * inv) * f.w;
                __nv_bfloat16 h0 = __float2bfloat16_rn(o0);
                __nv_bfloat16 h1 = __float2bfloat16_rn(o1);
                __nv_bfloat16 h2 = __float2bfloat16_rn(o2);
                __nv_bfloat16 h3 = __float2bfloat16_rn(o3);
                hv = (ull_t)__bfloat16_as_ushort(h0)
                   | ((ull_t)__bfloat16_as_ushort(h1) << 16)
                   | ((ull_t)__bfloat16_as_ushort(h2) << 32)
                   | ((ull_t)__bfloat16_as_ushort(h3) << 48);
                __nv_bfloat16 l0 = __float2bfloat16_rn(o0 - __bfloat162float(h0));
                __nv_bfloat16 l1 = __float2bfloat16_rn(o1 - __bfloat162float(h1));
                __nv_bfloat16 l2 = __float2bfloat16_rn(o2 - __bfloat162float(h2));
                __nv_bfloat16 l3 = __float2bfloat16_rn(o3 - __bfloat162float(h3));
                lv = (ull_t)__bfloat16_as_ushort(l0)
                   | ((ull_t)__bfloat16_as_ushort(l1) << 16)
                   | ((ull_t)__bfloat16_as_ushort(l2) << 32)
                   | ((ull_t)__bfloat16_as_ushort(l3) << 48);
            }
            *(ull_t*)&Ah[r * PA + cg * 4] = hv;
            *(ull_t*)&Al[r * PA + cg * 4] = lv;
        }
    }
    __syncthreads();

    // --- warp-tiled mma.sync mainloop: warp = 32(M) x 64(N), frags 2 x 8 ---
    const int wm = wid & 3;        // M quadrant (32 rows)
    const int wn = wid >> 2;       // N half (64 cols)
    const int g  = lid >> 2;       // 0..7
    const int c2 = (lid & 3) * 2;  // 0,2,4,6

    float acc[2][8][4];
    #pragma unroll
    for (int i = 0; i < 2; i++)
        #pragma unroll
        for (int j = 0; j < 8; j++)
            #pragma unroll
            for (int q = 0; q < 4; q++) acc[i][j][q] = 0.f;

    #pragma unroll
    for (int kc = 0; kc < 8; kc++) {
        const int k0 = kc * 16;
        uint32_t ah[2][4], al[2][4];
        #pragma unroll
        for (int i = 0; i < 2; i++) {
            int r = wm * 32 + i * 16 + g;
            const unsigned short* pa = &Ah[r * PA + k0 + c2];
            ah[i][0] = *(const uint32_t*)pa;
            ah[i][1] = *(const uint32_t*)(pa + 8 * PA);
            ah[i][2] = *(const uint32_t*)(pa + 8);
            ah[i][3] = *(const uint32_t*)(pa + 8 * PA + 8);
            const unsigned short* pl = &Al[r * PA + k0 + c2];
            al[i][0] = *(const uint32_t*)pl;
            al[i][1] = *(const uint32_t*)(pl + 8 * PA);
            al[i][2] = *(const uint32_t*)(pl + 8);
            al[i][3] = *(const uint32_t*)(pl + 8 * PA + 8);
        }
        #pragma unroll
        for (int j = 0; j < 8; j++) {
            int n = wn * 64 + j * 8 + g;
            const unsigned short* pb = &Bh[n * PB + k0 + c2];
            uint32_t bh0 = *(const uint32_t*)pb;
            uint32_t bh1 = *(const uint32_t*)(pb + 8);
            const unsigned short* ql = &Bl[n * PB + k0 + c2];
            uint32_t bl0 = *(const uint32_t*)ql;
            uint32_t bl1 = *(const uint32_t*)(ql + 8);
            #pragma unroll
            for (int i = 0; i < 2; i++) {
                mma16816(acc[i][j], ah[i], bh0, bh1);   // hi*hi
                mma16816(acc[i][j], al[i], bh0, bh1);   // lo*hi
                mma16816(acc[i][j], ah[i], bl0, bl1);   // hi*lo
            }
        }
    }

    // --- epilogue: bias add, store h, BN partial sums ---
    #pragma unroll
    for (int i = 0; i < 2; i++) {
        int r0l = wm * 32 + i * 16 + g;        // local row of c0/c1
        int r1l = r0l + 8;                     // local row of c2/c3
        bool v0 = r0l < rows, v1 = r1l < rows;
        #pragma unroll
        for (int j = 0; j < 8; j++) {
            int col = wn * 64 + j * 8 + c2;
            float b0 = s_bias[col], b1 = s_bias[col + 1];
            float h00 = v0 ? acc[i][j][0] + b0 : 0.f;
            float h01 = v0 ? acc[i][j][1] + b1 : 0.f;
            float h10 = v1 ? acc[i][j][2] + b0 : 0.f;
            float h11 = v1 ? acc[i][j][3] + b1 : 0.f;
            if (v0) {
                float2* p = (float2*)&out[(size_t)(row0 + r0l) * (S_NUM * C_DIM)
                                          + si * C_DIM + col];
                *p = make_float2(h00, h01);
            }
            if (v1) {
                float2* p = (float2*)&out[(size_t)(row0 + r1l) * (S_NUM * C_DIM)
                                          + si * C_DIM + col];
                *p = make_float2(h10, h11);
            }
            float s0 = h00 + h10, s1 = h01 + h11;
            float q0 = h00 * h00 + h10 * h10, q1 = h01 * h01 + h11 * h11;
            #pragma unroll
            for (int o = 4; o < 32; o <<= 1) {
                s0 += __shfl_xor_sync(0xffffffffu, s0, o);
                s1 += __shfl_xor_sync(0xffffffffu, s1, o);
                q0 += __shfl_xor_sync(0xffffffffu, q0, o);
                q1 += __shfl_xor_sync(0xffffffffu, q1, o);
            }
            if (g == 0) {
                atomicAdd(&s_sum[col], s0);
                atomicAdd(&s_sq[col], q0);
                atomicAdd(&s_sum[col + 1], s1);
                atomicAdd(&s_sq[col + 1], q1);
            }
        }
    }
    __syncthreads();
    if (tid < 128) {
        atomicAdd(&g_ch_sum[si * C_DIM + tid], s_sum[tid]);
        atomicAdd(&g_ch_sumsq[si * C_DIM + tid], s_sq[tid]);
    }
}

// ---------------- BN finalize: per (scale, channel) affine ----------------
__global__ void finalize_kernel(const float* __restrict__ gamma,
                                const float* __restrict__ beta) {
    int i = blockIdx.x * blockDim.x + threadIdx.x;
    if (i >= S_NUM * C_DIM) return;
    const float invM = 1.0f / (float)M_PTS;
    float mu  = g_ch_sum[i] * invM;
    float var = g_ch_sumsq[i] * invM - mu * mu;
    float rstd = rsqrtf(var + 1e-5f);
    float a = rstd * __ldg(&gamma[i]);
    g_bn_scale[i] = a;
    g_bn_shift[i] = __ldg(&beta[i]) - mu * a;
}

// ---------------- BN apply + LeakyReLU over whole output ----------------
__global__ void bn_apply_kernel(float* __restrict__ out) {
    long long i = (long long)blockIdx.x * blockDim.x + threadIdx.x;
    if (i >= (long long)M_PTS * 128) return;           // float4 granularity
    int sc4 = (int)(i & 127);                           // float4 index into [512]
    float4 h = ((float4*)out)[i];
    float4 a = ((const float4*)g_bn_scale)[sc4];
    float4 b = ((const float4*)g_bn_shift)[sc4];
    float x0 = h.x * a.x + b.x;
    float x1 = h.y * a.y + b.y;
    float x2 = h.z * a.z + b.z;
    float x3 = h.w * a.w + b.w;
    x0 = x0 > 0.f ? x0 : 0.01f * x0;
    x1 = x1 > 0.f ? x1 : 0.01f * x1;
    x2 = x2 > 0.f ? x2 : 0.01f * x2;
    x3 = x3 > 0.f ? x3 : 0.01f * x3;
    ((float4*)out)[i] = make_float4(x0, x1, x2, x3);
}

// ---------------- launch ----------------
extern "C" void kernel_launch(void* const* d_in, const int* in_sizes, int n_in,
                              void* d_out, int out_size) {
    const float* feats   = (const float*)d_in[0];
    const int*   indices = (const int*)d_in[1];
    const float* W       = (const float*)d_in[2];
    const float* b       = (const float*)d_in[3];
    const float* gamma   = (const float*)d_in[4];
    const float* beta    = (const float*)d_in[5];
    float* out = (float*)d_out;

    const int gemm_smem = (2 * 128 * PA + 2 * 128 * PB) * 2;   // 140288 B
    cudaFuncSetAttribute(gemm_tc_kernel,
                         cudaFuncAttributeMaxDynamicSharedMemorySize, gemm_smem);

    clear_stats_kernel<<<1, 512>>>();
    prep_w_kernel<<<S_NUM, 256>>>(W);

    const int shifts[S_NUM] = {1, 2, 3, 4};            // scales 2,4,8,16
    for (int si = 0; si < S_NUM; si++) {
        clear_used_kernel<<<(M_PTS * 32 + 255) / 256, 256>>>();
        clear_hash_kernel<<<(int)((HASH_SIZE + 255) / 256), 256>>>();
        assign_kernel<<<(M_PTS + 255) / 256, 256>>>(indices, shifts[si]);
        accumulate_kernel<<<(M_PTS * 32 + 255) / 256, 256>>>(feats);
        gemm_tc_kernel<<<(M_PTS + 127) / 128, 256, gemm_smem>>>(feats, b, out, si);
    }
    finalize_kernel<<<1, 512>>>(gamma, beta);
    bn_apply_kernel<<<(int)(((long long)M_PTS * 128 + 255) / 256), 256>>>(out);
}

// round 9
// speedup vs baseline: 1.8759x; 1.5959x over previous
#include <cuda_runtime.h>
#include <cuda_bf16.h>
#include <cstdint>

#define M_PTS 300000
#define C_DIM 128
#define S_NUM 4
#define HASH_SIZE (1u << 20)
#define HASH_MASK (HASH_SIZE - 1u)

#define PA 136   // A-tile pitch in bf16 elements (128 + 8 pad)
#define PB 138   // B-tile pitch in bf16 elements (128 + 10 pad)

typedef unsigned long long ull_t;

// ---------------- scratch (static device globals; no allocation) ----------------
__device__ ull_t        g_hash[HASH_SIZE];              // packed (key<<32 | id), ~0 = empty
__device__ int          g_point_bucket[M_PTS];
__device__ int          g_bucket_count[M_PTS];
__device__ float        g_bucket_sums[(size_t)M_PTS * C_DIM];   // 153.6 MB
__device__ float        g_ch_sum[S_NUM * C_DIM];
__device__ float        g_ch_sumsq[S_NUM * C_DIM];
__device__ float        g_bn_scale[S_NUM * C_DIM];
__device__ float        g_bn_shift[S_NUM * C_DIM];
// prepped W tiles: [si][n][PB] bf16, hi and lo parts (transposed: W[k][n] -> B[n][k])
__device__ __align__(16) unsigned short g_Whi[S_NUM * C_DIM * PB];
__device__ __align__(16) unsigned short g_Wlo[S_NUM * C_DIM * PB];

// ---------------- clears ----------------
__global__ void clear_stats_kernel() {
    int i = threadIdx.x;
    if (i < S_NUM * C_DIM) { g_ch_sum[i] = 0.f; g_ch_sumsq[i] = 0.f; }
}

// hash + per-scale counts clear (counts fully; 1.2 MB)
__global__ void clear_hash_kernel() {
    unsigned int i = blockIdx.x * blockDim.x + threadIdx.x;
    if (i < HASH_SIZE) g_hash[i] = ~0ull;
    if (i < M_PTS) g_bucket_count[i] = 0;
}

// zero sums only for multi-point buckets (singletons are never read)
__global__ void clear_sums_kernel() {
    int t = blockIdx.x * blockDim.x + threadIdx.x;
    if (t >= M_PTS * 32) return;
    int id = t >> 5;
    if (__ldg(&g_bucket_count[id]) > 1)
        ((float4*)g_bucket_sums)[t] = make_float4(0.f, 0.f, 0.f, 0.f);
}

// ---------------- W prep: transpose + bf16 hi/lo split, once per scale ----------------
__global__ void prep_w_kernel(const float* __restrict__ W) {
    int si = blockIdx.x;
    for (int it = threadIdx.x; it < C_DIM * PB; it += blockDim.x) {
        int n = it / PB;
        int k = it - n * PB;
        unsigned short hi = 0, lo = 0;
        if (k < C_DIM) {
            float v = __ldg(&W[((size_t)si * C_DIM + k) * C_DIM + n]);
            __nv_bfloat16 h = __float2bfloat16_rn(v);
            float l = v - __bfloat162float(h);
            hi = __bfloat16_as_ushort(h);
            lo = __bfloat16_as_ushort(__float2bfloat16_rn(l));
        }
        g_Whi[si * C_DIM * PB + it] = hi;
        g_Wlo[si * C_DIM * PB + it] = lo;
    }
}

// ---------------- bucket assignment: 64-bit packed hash insert, no spin ----------------
// id of a bucket = point index of the CAS winner (distinct, < M_PTS).
__global__ void assign_kernel(const int* __restrict__ indices, int shift) {
    int p = blockIdx.x * blockDim.x + threadIdx.x;
    if (p >= M_PTS) return;
    int4 v = ((const int4*)indices)[p];               // batch, x, y, z
    unsigned int cx = ((unsigned int)v.y) >> shift;
    unsigned int cy = ((unsigned int)v.z) >> shift;
    unsigned int cz = ((unsigned int)v.w) >> shift;
    unsigned int key = (((unsigned int)v.x * 512u + cx) * 512u + cy) * 512u + cz;

    ull_t desired = ((ull_t)key << 32) | (unsigned int)p;
    unsigned int slot = (key * 2654435761u) & HASH_MASK;
    int id;
    while (true) {
        ull_t prev = atomicCAS(&g_hash[slot], ~0ull, desired);
        if (prev == ~0ull) { id = p; break; }
        if ((unsigned int)(prev >> 32) == key) { id = (int)(unsigned int)prev; break; }
        slot = (slot + 1u) & HASH_MASK;
    }
    g_point_bucket[p] = id;
    atomicAdd(&g_bucket_count[id], 1);
}

// ---------------- scatter-add feats into bucket sums (multi buckets only) ----------------
__global__ void accumulate_kernel(const float* __restrict__ feats) {
    int t = blockIdx.x * blockDim.x + threadIdx.x;
    if (t >= M_PTS * 32) return;                       // 32 float4 groups per point
    int p = t >> 5;
    int cg = t & 31;
    int b = __ldg(&g_point_bucket[p]);
    if (__ldg(&g_bucket_count[b]) == 1) return;        // singleton: Os == 0, skip
    float4 f = ((const float4*)feats)[t];
    float* dst = &g_bucket_sums[(size_t)b * C_DIM + cg * 4];
    atomicAdd(dst + 0, f.x);
    atomicAdd(dst + 1, f.y);
    atomicAdd(dst + 2, f.z);
    atomicAdd(dst + 3, f.w);
}

// ---------------- HMMA GEMM: Os build + 3x bf16-split mma.sync + BN-stat epilogue ----
__device__ __forceinline__ void mma16816(float* c, const uint32_t* a,
                                         uint32_t b0, uint32_t b1) {
    asm volatile(
        "mma.sync.aligned.m16n8k16.row.col.f32.bf16.bf16.f32 "
        "{%0,%1,%2,%3}, {%4,%5,%6,%7}, {%8,%9}, {%0,%1,%2,%3};"
        : "+f"(c[0]), "+f"(c[1]), "+f"(c[2]), "+f"(c[3])
        : "r"(a[0]), "r"(a[1]), "r"(a[2]), "r"(a[3]), "r"(b0), "r"(b1));
}

__global__ void __launch_bounds__(256, 1)
gemm_tc_kernel(const float* __restrict__ feats, const float* __restrict__ bias,
               float* __restrict__ out, int si)
{
    extern __shared__ __align__(16) char smraw[];
    unsigned short* Ah = (unsigned short*)smraw;        // [128][PA]
    unsigned short* Al = Ah + 128 * PA;
    unsigned short* Bh = Al + 128 * PA;                 // [128][PB]
    unsigned short* Bl = Bh + 128 * PB;

    __shared__ float s_sum[128];
    __shared__ float s_sq[128];
    __shared__ float s_bias[128];
    __shared__ float s_inv[128];
    __shared__ int   s_bkt[128];                        // bucket id, or -1 if singleton/oob

    int tid = threadIdx.x;
    int wid = tid >> 5;
    int lid = tid & 31;

    int row0 = blockIdx.x * 128;
    int rows = M_PTS - row0; if (rows > 128) rows = 128;

    if (tid < 128) {
        s_sum[tid] = 0.f; s_sq[tid] = 0.f;
        s_bias[tid] = __ldg(&bias[si * C_DIM + tid]);
        int b = -1; float inv = 0.f;
        if (tid < rows) {
            b = __ldg(&g_point_bucket[row0 + tid]);
            int c = __ldg(&g_bucket_count[b]);
            if (c == 1) b = -1;                         // singleton: Os row == 0
            else inv = 1.0f / (float)c;
        }
        s_bkt[tid] = b; s_inv[tid] = inv;
    }
    __syncthreads();

    // --- B tiles: flat vectorized copy of prepped W (already transposed + split) ---
    {
        const uint4* srcH = (const uint4*)(g_Whi + (size_t)si * C_DIM * PB);
        const uint4* srcL = (const uint4*)(g_Wlo + (size_t)si * C_DIM * PB);
        uint4* dH = (uint4*)Bh;
        uint4* dL = (uint4*)Bl;
        const int nvec = C_DIM * PB * 2 / 16;          // 2208
        for (int it = tid; it < nvec; it += 256) {
            dH[it] = srcH[it];
            dL[it] = srcL[it];
        }
    }

    // --- A tile: Os = (f - mean)*f, split bf16 hi/lo (zero for singleton rows) ---
    {
        const float4* f4 = (const float4*)feats;
        const float4* s4 = (const float4*)g_bucket_sums;
        for (int it = tid; it < 4096; it += 256) {
            int r = it >> 5, cg = it & 31;
            ull_t hv = 0ull, lv = 0ull;
            int bkt = (r < rows) ? s_bkt[r] : -1;
            if (bkt >= 0) {
                int p = row0 + r;
                float4 f = f4[(size_t)p * 32 + cg];
                float4 su = s4[(size_t)bkt * 32 + cg];
                float inv = s_inv[r];
                float o0 = (f.x - su.x * inv) * f.x;
                float o1 = (f.y - su.y * inv) * f.y;
                float o2 = (f.z - su.z * inv) * f.z;
                float o3 = (f.w - su.w * inv) * f.w;
                __nv_bfloat16 h0 = __float2bfloat16_rn(o0);
                __nv_bfloat16 h1 = __float2bfloat16_rn(o1);
                __nv_bfloat16 h2 = __float2bfloat16_rn(o2);
                __nv_bfloat16 h3 = __float2bfloat16_rn(o3);
                hv = (ull_t)__bfloat16_as_ushort(h0)
                   | ((ull_t)__bfloat16_as_ushort(h1) << 16)
                   | ((ull_t)__bfloat16_as_ushort(h2) << 32)
                   | ((ull_t)__bfloat16_as_ushort(h3) << 48);
                __nv_bfloat16 l0 = __float2bfloat16_rn(o0 - __bfloat162float(h0));
                __nv_bfloat16 l1 = __float2bfloat16_rn(o1 - __bfloat162float(h1));
                __nv_bfloat16 l2 = __float2bfloat16_rn(o2 - __bfloat162float(h2));
                __nv_bfloat16 l3 = __float2bfloat16_rn(o3 - __bfloat162float(h3));
                lv = (ull_t)__bfloat16_as_ushort(l0)
                   | ((ull_t)__bfloat16_as_ushort(l1) << 16)
                   | ((ull_t)__bfloat16_as_ushort(l2) << 32)
                   | ((ull_t)__bfloat16_as_ushort(l3) << 48);
            }
            *(ull_t*)&Ah[r * PA + cg * 4] = hv;
            *(ull_t*)&Al[r * PA + cg * 4] = lv;
        }
    }
    __syncthreads();

    // --- warp-tiled mma.sync mainloop: warp = 32(M) x 64(N), frags 2 x 8 ---
    const int wm = wid & 3;        // M quadrant (32 rows)
    const int wn = wid >> 2;       // N half (64 cols)
    const int g  = lid >> 2;       // 0..7
    const int c2 = (lid & 3) * 2;  // 0,2,4,6

    float acc[2][8][4];
    #pragma unroll
    for (int i = 0; i < 2; i++)
        #pragma unroll
        for (int j = 0; j < 8; j++)
            #pragma unroll
            for (int q = 0; q < 4; q++) acc[i][j][q] = 0.f;

    #pragma unroll
    for (int kc = 0; kc < 8; kc++) {
        const int k0 = kc * 16;
        uint32_t ah[2][4], al[2][4];
        #pragma unroll
        for (int i = 0; i < 2; i++) {
            int r = wm * 32 + i * 16 + g;
            const unsigned short* pa = &Ah[r * PA + k0 + c2];
            ah[i][0] = *(const uint32_t*)pa;
            ah[i][1] = *(const uint32_t*)(pa + 8 * PA);
            ah[i][2] = *(const uint32_t*)(pa + 8);
            ah[i][3] = *(const uint32_t*)(pa + 8 * PA + 8);
            const unsigned short* pl = &Al[r * PA + k0 + c2];
            al[i][0] = *(const uint32_t*)pl;
            al[i][1] = *(const uint32_t*)(pl + 8 * PA);
            al[i][2] = *(const uint32_t*)(pl + 8);
            al[i][3] = *(const uint32_t*)(pl + 8 * PA + 8);
        }
        #pragma unroll
        for (int j = 0; j < 8; j++) {
            int n = wn * 64 + j * 8 + g;
            const unsigned short* pb = &Bh[n * PB + k0 + c2];
            uint32_t bh0 = *(const uint32_t*)pb;
            uint32_t bh1 = *(const uint32_t*)(pb + 8);
            const unsigned short* ql = &Bl[n * PB + k0 + c2];
            uint32_t bl0 = *(const uint32_t*)ql;
            uint32_t bl1 = *(const uint32_t*)(ql + 8);
            #pragma unroll
            for (int i = 0; i < 2; i++) {
                mma16816(acc[i][j], ah[i], bh0, bh1);   // hi*hi
                mma16816(acc[i][j], al[i], bh0, bh1);   // lo*hi
                mma16816(acc[i][j], ah[i], bl0, bl1);   // hi*lo
            }
        }
    }

    // --- epilogue: bias add, store h, BN partial sums ---
    #pragma unroll
    for (int i = 0; i < 2; i++) {
        int r0l = wm * 32 + i * 16 + g;        // local row of c0/c1
        int r1l = r0l + 8;                     // local row of c2/c3
        bool v0 = r0l < rows, v1 = r1l < rows;
        #pragma unroll
        for (int j = 0; j < 8; j++) {
            int col = wn * 64 + j * 8 + c2;
            float b0 = s_bias[col], b1 = s_bias[col + 1];
            float h00 = v0 ? acc[i][j][0] + b0 : 0.f;
            float h01 = v0 ? acc[i][j][1] + b1 : 0.f;
            float h10 = v1 ? acc[i][j][2] + b0 : 0.f;
            float h11 = v1 ? acc[i][j][3] + b1 : 0.f;
            if (v0) {
                float2* p = (float2*)&out[(size_t)(row0 + r0l) * (S_NUM * C_DIM)
                                          + si * C_DIM + col];
                *p = make_float2(h00, h01);
            }
            if (v1) {
                float2* p = (float2*)&out[(size_t)(row0 + r1l) * (S_NUM * C_DIM)
                                          + si * C_DIM + col];
                *p = make_float2(h10, h11);
            }
            float s0 = h00 + h10, s1 = h01 + h11;
            float q0 = h00 * h00 + h10 * h10, q1 = h01 * h01 + h11 * h11;
            #pragma unroll
            for (int o = 4; o < 32; o <<= 1) {
                s0 += __shfl_xor_sync(0xffffffffu, s0, o);
                s1 += __shfl_xor_sync(0xffffffffu, s1, o);
                q0 += __shfl_xor_sync(0xffffffffu, q0, o);
                q1 += __shfl_xor_sync(0xffffffffu, q1, o);
            }
            if (g == 0) {
                atomicAdd(&s_sum[col], s0);
                atomicAdd(&s_sq[col], q0);
                atomicAdd(&s_sum[col + 1], s1);
                atomicAdd(&s_sq[col + 1], q1);
            }
        }
    }
    __syncthreads();
    if (tid < 128) {
        atomicAdd(&g_ch_sum[si * C_DIM + tid], s_sum[tid]);
        atomicAdd(&g_ch_sumsq[si * C_DIM + tid], s_sq[tid]);
    }
}

// ---------------- BN finalize: per (scale, channel) affine ----------------
__global__ void finalize_kernel(const float* __restrict__ gamma,
                                const float* __restrict__ beta) {
    int i = blockIdx.x * blockDim.x + threadIdx.x;
    if (i >= S_NUM * C_DIM) return;
    const float invM = 1.0f / (float)M_PTS;
    float mu  = g_ch_sum[i] * invM;
    float var = g_ch_sumsq[i] * invM - mu * mu;
    float rstd = rsqrtf(var + 1e-5f);
    float a = rstd * __ldg(&gamma[i]);
    g_bn_scale[i] = a;
    g_bn_shift[i] = __ldg(&beta[i]) - mu * a;
}

// ---------------- BN apply + LeakyReLU over whole output ----------------
__global__ void bn_apply_kernel(float* __restrict__ out) {
    long long i = (long long)blockIdx.x * blockDim.x + threadIdx.x;
    if (i >= (long long)M_PTS * 128) return;           // float4 granularity
    int sc4 = (int)(i & 127);                           // float4 index into [512]
    float4 h = ((float4*)out)[i];
    float4 a = ((const float4*)g_bn_scale)[sc4];
    float4 b = ((const float4*)g_bn_shift)[sc4];
    float x0 = h.x * a.x + b.x;
    float x1 = h.y * a.y + b.y;
    float x2 = h.z * a.z + b.z;
    float x3 = h.w * a.w + b.w;
    x0 = x0 > 0.f ? x0 : 0.01f * x0;
    x1 = x1 > 0.f ? x1 : 0.01f * x1;
    x2 = x2 > 0.f ? x2 : 0.01f * x2;
    x3 = x3 > 0.f ? x3 : 0.01f * x3;
    ((float4*)out)[i] = make_float4(x0, x1, x2, x3);
}

// ---------------- launch ----------------
extern "C" void kernel_launch(void* const* d_in, const int* in_sizes, int n_in,
                              void* d_out, int out_size) {
    const float* feats   = (const float*)d_in[0];
    const int*   indices = (const int*)d_in[1];
    const float* W       = (const float*)d_in[2];
    const float* b       = (const float*)d_in[3];
    const float* gamma   = (const float*)d_in[4];
    const float* beta    = (const float*)d_in[5];
    float* out = (float*)d_out;

    const int gemm_smem = (2 * 128 * PA + 2 * 128 * PB) * 2;   // 140288 B
    cudaFuncSetAttribute(gemm_tc_kernel,
                         cudaFuncAttributeMaxDynamicSharedMemorySize, gemm_smem);

    clear_stats_kernel<<<1, 512>>>();
    prep_w_kernel<<<S_NUM, 256>>>(W);

    const int shifts[S_NUM] = {1, 2, 3, 4};            // scales 2,4,8,16
    for (int si = 0; si < S_NUM; si++) {
        clear_hash_kernel<<<(int)((HASH_SIZE + 255) / 256), 256>>>();
        assign_kernel<<<(M_PTS + 255) / 256, 256>>>(indices, shifts[si]);
        clear_sums_kernel<<<(M_PTS * 32 + 255) / 256, 256>>>();
        accumulate_kernel<<<(M_PTS * 32 + 255) / 256, 256>>>(feats);
        gemm_tc_kernel<<<(M_PTS + 127) / 128, 256, gemm_smem>>>(feats, b, out, si);
    }
    finalize_kernel<<<1, 512>>>(gamma, beta);
    bn_apply_kernel<<<(int)(((long long)M_PTS * 128 + 255) / 256), 256>>>(out);
}

// round 13
// speedup vs baseline: 2.4963x; 1.3307x over previous
#include <cuda_runtime.h>
#include <cuda_bf16.h>
#include <cstdint>

#define M_PTS 300000
#define C_DIM 128
#define S_NUM 4
#define HASH_SIZE (1u << 20)
#define HASH_MASK (HASH_SIZE - 1u)

#define PA 136   // A-tile pitch in bf16 elements (272 B, 16-aligned, LDSM conflict-free)
#define PB 136   // B-tile pitch in bf16 elements (MUST be 16B-aligned for ldmatrix)
#define TM 64    // GEMM tile rows

typedef unsigned long long ull_t;

// ---------------- scratch (static device globals; no allocation) ----------------
__device__ ull_t        g_hash[HASH_SIZE];              // packed (key<<32 | id), ~0 = empty
__device__ int          g_point_bucket[M_PTS];
__device__ int          g_bucket_count[M_PTS];
__device__ float        g_bucket_sums[(size_t)M_PTS * C_DIM];   // 153.6 MB
__device__ float        g_ch_sum[S_NUM * C_DIM];
__device__ float        g_ch_sumsq[S_NUM * C_DIM];
__device__ float        g_bn_scale[S_NUM * C_DIM];
__device__ float        g_bn_shift[S_NUM * C_DIM];
// prepped W tiles: [si][n][PB] bf16, hi and lo parts (transposed: W[k][n] -> B[n][k])
__device__ __align__(16) unsigned short g_Whi[S_NUM * C_DIM * PB];
__device__ __align__(16) unsigned short g_Wlo[S_NUM * C_DIM * PB];

// ---------------- helpers ----------------
__device__ __forceinline__ uint32_t smem_u32(const void* p) {
    uint32_t a;
    asm("{ .reg .u64 t; cvta.to.shared.u64 t, %1; cvt.u32.u64 %0, t; }" : "=r"(a) : "l"(p));
    return a;
}
#define LDSM_X4(r0, r1, r2, r3, addr) \
    asm volatile("ldmatrix.sync.aligned.m8n8.x4.shared.b16 {%0,%1,%2,%3}, [%4];" \
        : "=r"(r0), "=r"(r1), "=r"(r2), "=r"(r3) : "r"(addr))

__device__ __forceinline__ void mma16816(float* c, const uint32_t* a,
                                         uint32_t b0, uint32_t b1) {
    asm volatile(
        "mma.sync.aligned.m16n8k16.row.col.f32.bf16.bf16.f32 "
        "{%0,%1,%2,%3}, {%4,%5,%6,%7}, {%8,%9}, {%0,%1,%2,%3};"
        : "+f"(c[0]), "+f"(c[1]), "+f"(c[2]), "+f"(c[3])
        : "r"(a[0]), "r"(a[1]), "r"(a[2]), "r"(a[3]), "r"(b0), "r"(b1));
}
__device__ __forceinline__ uint32_t bf16x2_rn(float hi_el, float lo_el) {
    uint32_t d;
    asm("cvt.rn.bf16x2.f32 %0, %1, %2;" : "=r"(d) : "f"(hi_el), "f"(lo_el));
    return d;   // d.lo16 = lo_el, d.hi16 = hi_el
}

// ---------------- clears ----------------
__global__ void clear_stats_kernel() {
    int i = threadIdx.x;
    if (i < S_NUM * C_DIM) { g_ch_sum[i] = 0.f; g_ch_sumsq[i] = 0.f; }
}

__global__ void clear_hash_kernel() {
    unsigned int i = blockIdx.x * blockDim.x + threadIdx.x;
    if (i < HASH_SIZE) g_hash[i] = ~0ull;
    if (i < M_PTS) g_bucket_count[i] = 0;
}

// zero sums only for multi-point buckets (singletons are never read)
__global__ void clear_sums_kernel() {
    int t = blockIdx.x * blockDim.x + threadIdx.x;
    if (t >= M_PTS * 32) return;
    int id = t >> 5;
    if (__ldg(&g_bucket_count[id]) > 1)
        ((float4*)g_bucket_sums)[t] = make_float4(0.f, 0.f, 0.f, 0.f);
}

// ---------------- W prep: transpose + bf16 hi/lo split, once per scale ----------------
__global__ void prep_w_kernel(const float* __restrict__ W) {
    int si = blockIdx.x;
    for (int it = threadIdx.x; it < C_DIM * PB; it += blockDim.x) {
        int n = it / PB;
        int k = it - n * PB;
        unsigned short hi = 0, lo = 0;
        if (k < C_DIM) {
            float v = __ldg(&W[((size_t)si * C_DIM + k) * C_DIM + n]);
            __nv_bfloat16 h = __float2bfloat16_rn(v);
            float l = v - __bfloat162float(h);
            hi = __bfloat16_as_ushort(h);
            lo = __bfloat16_as_ushort(__float2bfloat16_rn(l));
        }
        g_Whi[si * C_DIM * PB + it] = hi;
        g_Wlo[si * C_DIM * PB + it] = lo;
    }
}

// ---------------- bucket assignment: 64-bit packed hash insert, no spin ----------------
__global__ void assign_kernel(const int* __restrict__ indices, int shift) {
    int p = blockIdx.x * blockDim.x + threadIdx.x;
    if (p >= M_PTS) return;
    int4 v = ((const int4*)indices)[p];               // batch, x, y, z
    unsigned int cx = ((unsigned int)v.y) >> shift;
    unsigned int cy = ((unsigned int)v.z) >> shift;
    unsigned int cz = ((unsigned int)v.w) >> shift;
    unsigned int key = (((unsigned int)v.x * 512u + cx) * 512u + cy) * 512u + cz;

    ull_t desired = ((ull_t)key << 32) | (unsigned int)p;
    unsigned int slot = (key * 2654435761u) & HASH_MASK;
    int id;
    while (true) {
        ull_t prev = atomicCAS(&g_hash[slot], ~0ull, desired);
        if (prev == ~0ull) { id = p; break; }
        if ((unsigned int)(prev >> 32) == key) { id = (int)(unsigned int)prev; break; }
        slot = (slot + 1u) & HASH_MASK;
    }
    g_point_bucket[p] = id;
    atomicAdd(&g_bucket_count[id], 1);
}

// ---------------- scatter-add feats into bucket sums (multi buckets only) ----------------
__global__ void accumulate_kernel(const float* __restrict__ feats) {
    int t = blockIdx.x * blockDim.x + threadIdx.x;
    if (t >= M_PTS * 32) return;                       // 32 float4 groups per point
    int p = t >> 5;
    int cg = t & 31;
    int b = __ldg(&g_point_bucket[p]);
    if (__ldg(&g_bucket_count[b]) == 1) return;        // singleton: Os == 0, skip
    float4 f = ((const float4*)feats)[t];
    float* dst = &g_bucket_sums[(size_t)b * C_DIM + cg * 4];
    atomicAdd(dst + 0, f.x);
    atomicAdd(dst + 1, f.y);
    atomicAdd(dst + 2, f.z);
    atomicAdd(dst + 3, f.w);
}

// ---------------- HMMA GEMM: 64x128 tile, ldmatrix + 3-term bf16 split ----------------
__global__ void __launch_bounds__(256, 2)
gemm_tc_kernel(const float* __restrict__ feats, const float* __restrict__ bias,
               float* __restrict__ out, int si)
{
    extern __shared__ __align__(16) char smraw[];
    unsigned short* Ah = (unsigned short*)smraw;        // [TM][PA]
    unsigned short* Al = Ah + TM * PA;
    unsigned short* Bh = Al + TM * PA;                  // [128][PB]
    unsigned short* Bl = Bh + 128 * PB;

    __shared__ float s_sum[128];
    __shared__ float s_sq[128];
    __shared__ float s_bias[128];
    __shared__ float s_inv[TM];
    __shared__ int   s_bkt[TM];                         // bucket id, or -1 if singleton/oob

    int tid = threadIdx.x;
    int wid = tid >> 5;
    int lid = tid & 31;

    int row0 = blockIdx.x * TM;
    int rows = M_PTS - row0; if (rows > TM) rows = TM;

    if (tid < 128) { s_sum[tid] = 0.f; s_sq[tid] = 0.f;
                     s_bias[tid] = __ldg(&bias[si * C_DIM + tid]); }
    int multi = 0;
    if (tid < TM) {
        int b = -1; float inv = 0.f;
        if (tid < rows) {
            b = __ldg(&g_point_bucket[row0 + tid]);
            int c = __ldg(&g_bucket_count[b]);
            if (c == 1) b = -1;                         // singleton: Os row == 0
            else { inv = 1.0f / (float)c; multi = 1; }
        }
        s_bkt[tid] = b; s_inv[tid] = inv;
    }
    int nmulti = __syncthreads_count(multi);

    if (nmulti == 0) {
        // ---- fast path: every row singleton -> Os == 0 -> h = bias exactly ----
        const float4* b4 = (const float4*)s_bias;
        float4* o4 = (float4*)out;
        for (int i = tid; i < rows * 32; i += 256) {
            int r = i >> 5, cg = i & 31;
            o4[(size_t)(row0 + r) * 128 + si * 32 + cg] = b4[cg];
        }
        if (tid < 128) {
            float bv = s_bias[tid];
            atomicAdd(&g_ch_sum[si * C_DIM + tid], (float)rows * bv);
            atomicAdd(&g_ch_sumsq[si * C_DIM + tid], (float)rows * bv * bv);
        }
        return;
    }

    // --- B tiles: flat vectorized copy of prepped W (already transposed + split) ---
    {
        const uint4* srcH = (const uint4*)(g_Whi + (size_t)si * C_DIM * PB);
        const uint4* srcL = (const uint4*)(g_Wlo + (size_t)si * C_DIM * PB);
        uint4* dH = (uint4*)Bh;
        uint4* dL = (uint4*)Bl;
        const int nvec = C_DIM * PB * 2 / 16;          // 2176
        for (int it = tid; it < nvec; it += 256) {
            dH[it] = srcH[it];
            dL[it] = srcL[it];
        }
    }

    // --- A tile: Os = (f - mean)*f, truncation hi/lo split ---
    {
        const float4* f4 = (const float4*)feats;
        const float4* s4 = (const float4*)g_bucket_sums;
        for (int it = tid; it < TM * 32; it += 256) {
            int r = it >> 5, cg = it & 31;
            ull_t hv = 0ull, lv = 0ull;
            int bkt = (r < rows) ? s_bkt[r] : -1;
            if (bkt >= 0) {
                int p = row0 + r;
                float4 f = f4[(size_t)p * 32 + cg];
                float4 su = s4[(size_t)bkt * 32 + cg];
                float inv = s_inv[r];
                float o0 = (f.x - su.x * inv) * f.x;
                float o1 = (f.y - su.y * inv) * f.y;
                float o2 = (f.z - su.z * inv) * f.z;
                float o3 = (f.w - su.w * inv) * f.w;
                uint32_t u0 = __float_as_uint(o0), u1 = __float_as_uint(o1);
                uint32_t u2 = __float_as_uint(o2), u3 = __float_as_uint(o3);
                uint32_t h01 = __byte_perm(u0, u1, 0x7632);
                uint32_t h23 = __byte_perm(u2, u3, 0x7632);
                float l0 = o0 - __uint_as_float(u0 & 0xFFFF0000u);
                float l1 = o1 - __uint_as_float(u1 & 0xFFFF0000u);
                float l2 = o2 - __uint_as_float(u2 & 0xFFFF0000u);
                float l3 = o3 - __uint_as_float(u3 & 0xFFFF0000u);
                uint32_t lo01 = bf16x2_rn(l1, l0);
                uint32_t lo23 = bf16x2_rn(l3, l2);
                hv = (ull_t)h01 | ((ull_t)h23 << 32);
                lv = (ull_t)lo01 | ((ull_t)lo23 << 32);
            }
            *(ull_t*)&Ah[r * PA + cg * 4] = hv;
            *(ull_t*)&Al[r * PA + cg * 4] = lv;
        }
    }
    __syncthreads();

    // --- warp-tiled mainloop: warp = 16(M) x 64(N), ldmatrix fragment loads ---
    const int wm = wid & 3;        // M quadrant (16 rows)
    const int wn = wid >> 2;       // N half (64 cols)
    const int g  = lid >> 2;       // 0..7
    const int c2 = (lid & 3) * 2;  // 0,2,4,6

    const uint32_t AhU = smem_u32(Ah), AlU = smem_u32(Al);
    const uint32_t BhU = smem_u32(Bh), BlU = smem_u32(Bl);
    // A lane addr: rows wm*16 + (lid&15), col halves by lid>=16
    const uint32_t aoff = (uint32_t)(wm * 16 + (lid & 15)) * (PA * 2) + ((lid >> 4) * 16);
    // B lane addr: 4 tiles = {j,k0},{j,k0+8},{j+1,k0},{j+1,k0+8}
    const uint32_t boff = (uint32_t)(wn * 64 + (lid & 7) + ((lid >> 4) * 8)) * (PB * 2)
                        + (((lid >> 3) & 1) * 16);

    float acc[8][4];
    #pragma unroll
    for (int j = 0; j < 8; j++)
        #pragma unroll
        for (int q = 0; q < 4; q++) acc[j][q] = 0.f;

    #pragma unroll
    for (int kc = 0; kc < 8; kc++) {
        uint32_t ah[4], al[4];
        LDSM_X4(ah[0], ah[1], ah[2], ah[3], AhU + aoff + kc * 32);
        LDSM_X4(al[0], al[1], al[2], al[3], AlU + aoff + kc * 32);
        #pragma unroll
        for (int jp = 0; jp < 4; jp++) {
            uint32_t bh[4], bl[4];
            uint32_t ba = boff + (uint32_t)jp * (16 * PB * 2) + kc * 32;
            LDSM_X4(bh[0], bh[1], bh[2], bh[3], BhU + ba);
            LDSM_X4(bl[0], bl[1], bl[2], bl[3], BlU + ba);
            mma16816(acc[2 * jp],     ah, bh[0], bh[1]);   // hi*hi
            mma16816(acc[2 * jp],     al, bh[0], bh[1]);   // lo*hi
            mma16816(acc[2 * jp],     ah, bl[0], bl[1]);   // hi*lo
            mma16816(acc[2 * jp + 1], ah, bh[2], bh[3]);
            mma16816(acc[2 * jp + 1], al, bh[2], bh[3]);
            mma16816(acc[2 * jp + 1], ah, bl[2], bl[3]);
        }
    }

    // --- epilogue: bias add, store h, BN partial sums ---
    {
        int r0l = wm * 16 + g;                 // local row of c0/c1
        int r1l = r0l + 8;                     // local row of c2/c3
        bool v0 = r0l < rows, v1 = r1l < rows;
        #pragma unroll
        for (int j = 0; j < 8; j++) {
            int col = wn * 64 + j * 8 + c2;
            float b0 = s_bias[col], b1 = s_bias[col + 1];
            float h00 = v0 ? acc[j][0] + b0 : 0.f;
            float h01 = v0 ? acc[j][1] + b1 : 0.f;
            float h10 = v1 ? acc[j][2] + b0 : 0.f;
            float h11 = v1 ? acc[j][3] + b1 : 0.f;
            if (v0) {
                float2* p = (float2*)&out[(size_t)(row0 + r0l) * (S_NUM * C_DIM)
                                          + si * C_DIM + col];
                *p = make_float2(h00, h01);
            }
            if (v1) {
                float2* p = (float2*)&out[(size_t)(row0 + r1l) * (S_NUM * C_DIM)
                                          + si * C_DIM + col];
                *p = make_float2(h10, h11);
            }
            float s0 = h00 + h10, s1 = h01 + h11;
            float q0 = h00 * h00 + h10 * h10, q1 = h01 * h01 + h11 * h11;
            #pragma unroll
            for (int o = 4; o < 32; o <<= 1) {
                s0 += __shfl_xor_sync(0xffffffffu, s0, o);
                s1 += __shfl_xor_sync(0xffffffffu, s1, o);
                q0 += __shfl_xor_sync(0xffffffffu, q0, o);
                q1 += __shfl_xor_sync(0xffffffffu, q1, o);
            }
            if (g == 0) {
                atomicAdd(&s_sum[col], s0);
                atomicAdd(&s_sq[col], q0);
                atomicAdd(&s_sum[col + 1], s1);
                atomicAdd(&s_sq[col + 1], q1);
            }
        }
    }
    __syncthreads();
    if (tid < 128) {
        atomicAdd(&g_ch_sum[si * C_DIM + tid], s_sum[tid]);
        atomicAdd(&g_ch_sumsq[si * C_DIM + tid], s_sq[tid]);
    }
}

// ---------------- BN finalize: per (scale, channel) affine ----------------
__global__ void finalize_kernel(const float* __restrict__ gamma,
                                const float* __restrict__ beta) {
    int i = blockIdx.x * blockDim.x + threadIdx.x;
    if (i >= S_NUM * C_DIM) return;
    const float invM = 1.0f / (float)M_PTS;
    float mu  = g_ch_sum[i] * invM;
    float var = g_ch_sumsq[i] * invM - mu * mu;
    float rstd = rsqrtf(var + 1e-5f);
    float a = rstd * __ldg(&gamma[i]);
    g_bn_scale[i] = a;
    g_bn_shift[i] = __ldg(&beta[i]) - mu * a;
}

// ---------------- BN apply + LeakyReLU over whole output ----------------
__global__ void bn_apply_kernel(float* __restrict__ out) {
    long long i = (long long)blockIdx.x * blockDim.x + threadIdx.x;
    if (i >= (long long)M_PTS * 128) return;           // float4 granularity
    int sc4 = (int)(i & 127);                           // float4 index into [512]
    float4 h = ((float4*)out)[i];
    float4 a = ((const float4*)g_bn_scale)[sc4];
    float4 b = ((const float4*)g_bn_shift)[sc4];
    float x0 = h.x * a.x + b.x;
    float x1 = h.y * a.y + b.y;
    float x2 = h.z * a.z + b.z;
    float x3 = h.w * a.w + b.w;
    x0 = x0 > 0.f ? x0 : 0.01f * x0;
    x1 = x1 > 0.f ? x1 : 0.01f * x1;
    x2 = x2 > 0.f ? x2 : 0.01f * x2;
    x3 = x3 > 0.f ? x3 : 0.01f * x3;
    ((float4*)out)[i] = make_float4(x0, x1, x2, x3);
}

// ---------------- launch ----------------
extern "C" void kernel_launch(void* const* d_in, const int* in_sizes, int n_in,
                              void* d_out, int out_size) {
    const float* feats   = (const float*)d_in[0];
    const int*   indices = (const int*)d_in[1];
    const float* W       = (const float*)d_in[2];
    const float* b       = (const float*)d_in[3];
    const float* gamma   = (const float*)d_in[4];
    const float* beta    = (const float*)d_in[5];
    float* out = (float*)d_out;

    const int gemm_smem = (2 * TM * PA + 2 * 128 * PB) * 2;   // 104448 B
    cudaFuncSetAttribute(gemm_tc_kernel,
                         cudaFuncAttributeMaxDynamicSharedMemorySize, gemm_smem);

    clear_stats_kernel<<<1, 512>>>();
    prep_w_kernel<<<S_NUM, 256>>>(W);

    const int shifts[S_NUM] = {1, 2, 3, 4};            // scales 2,4,8,16
    for (int si = 0; si < S_NUM; si++) {
        clear_hash_kernel<<<(int)((HASH_SIZE + 255) / 256), 256>>>();
        assign_kernel<<<(M_PTS + 255) / 256, 256>>>(indices, shifts[si]);
        clear_sums_kernel<<<(M_PTS * 32 + 255) / 256, 256>>>();
        accumulate_kernel<<<(M_PTS * 32 + 255) / 256, 256>>>(feats);
        gemm_tc_kernel<<<(M_PTS + TM - 1) / TM, 256, gemm_smem>>>(feats, b, out, si);
    }
    finalize_kernel<<<1, 512>>>(gamma, beta);
    bn_apply_kernel<<<(int)(((long long)M_PTS * 128 + 255) / 256), 256>>>(out);
}

// round 15
// speedup vs baseline: 2.9645x; 1.1876x over previous
#include <cuda_runtime.h>
#include <cuda_bf16.h>
#include <cstdint>

#define M_PTS 300000
#define C_DIM 128
#define S_NUM 4
#define HASH_SIZE (1u << 22)
#define HASH_MASK (HASH_SIZE - 1u)

#define PA 136   // A-tile pitch in bf16 elements (272 B, 16-aligned, LDSM conflict-free)
#define PB 136   // B-tile pitch in bf16 elements (MUST be 16B-aligned for ldmatrix)
#define TM 64    // GEMM tile rows
#define NBLOCKS ((M_PTS + TM - 1) / TM)
#define GEMM_GRID 296                                  // 2 CTAs/SM x 148 SMs (<= NBLOCKS)

typedef unsigned long long ull_t;

// ---------------- scratch (static device globals; no allocation) ----------------
__device__ ull_t        g_hash[HASH_SIZE];              // packed (key32<<32 | id), ~0 = empty
__device__ int          g_point_bucket[S_NUM * M_PTS];
__device__ int          g_bucket_count[S_NUM * M_PTS];
__device__ float        g_bucket_sums[(size_t)M_PTS * C_DIM];   // 153.6 MB, reused per scale
__device__ float        g_ch_sum[S_NUM * C_DIM];
__device__ float        g_ch_sumsq[S_NUM * C_DIM];
__device__ float        g_bn_scale[S_NUM * C_DIM];
__device__ float        g_bn_shift[S_NUM * C_DIM];
// prepped W tiles: [si][n][PB] bf16, hi and lo parts (transposed: W[k][n] -> B[n][k])
__device__ __align__(16) unsigned short g_Whi[S_NUM * C_DIM * PB];
__device__ __align__(16) unsigned short g_Wlo[S_NUM * C_DIM * PB];

// ---------------- helpers ----------------
__device__ __forceinline__ uint32_t smem_u32(const void* p) {
    uint32_t a;
    asm("{ .reg .u64 t; cvta.to.shared.u64 t, %1; cvt.u32.u64 %0, t; }" : "=r"(a) : "l"(p));
    return a;
}
#define LDSM_X4(r0, r1, r2, r3, addr) \
    asm volatile("ldmatrix.sync.aligned.m8n8.x4.shared.b16 {%0,%1,%2,%3}, [%4];" \
        : "=r"(r0), "=r"(r1), "=r"(r2), "=r"(r3) : "r"(addr))

__device__ __forceinline__ void mma16816(float* c, const uint32_t* a,
                                         uint32_t b0, uint32_t b1) {
    asm volatile(
        "mma.sync.aligned.m16n8k16.row.col.f32.bf16.bf16.f32 "
        "{%0,%1,%2,%3}, {%4,%5,%6,%7}, {%8,%9}, {%0,%1,%2,%3};"
        : "+f"(c[0]), "+f"(c[1]), "+f"(c[2]), "+f"(c[3])
        : "r"(a[0]), "r"(a[1]), "r"(a[2]), "r"(a[3]), "r"(b0), "r"(b1));
}
__device__ __forceinline__ uint32_t bf16x2_rn(float hi_el, float lo_el) {
    uint32_t d;
    asm("cvt.rn.bf16x2.f32 %0, %1, %2;" : "=r"(d) : "f"(hi_el), "f"(lo_el));
    return d;   // d.lo16 = lo_el, d.hi16 = hi_el
}

// ---------------- fused clear: hash + counts + BN stats ----------------
__global__ void clear_all_kernel() {
    unsigned int i = blockIdx.x * blockDim.x + threadIdx.x;
    if (i < HASH_SIZE) g_hash[i] = ~0ull;
    if (i < S_NUM * M_PTS) g_bucket_count[i] = 0;
    if (i < S_NUM * C_DIM) { g_ch_sum[i] = 0.f; g_ch_sumsq[i] = 0.f; }
}

// zero sums only for multi-point buckets of scale si (singletons are never read)
__global__ void clear_sums_kernel(int si) {
    int t = blockIdx.x * blockDim.x + threadIdx.x;
    if (t >= M_PTS * 32) return;
    int id = t >> 5;
    if (__ldg(&g_bucket_count[si * M_PTS + id]) > 1)
        ((float4*)g_bucket_sums)[t] = make_float4(0.f, 0.f, 0.f, 0.f);
}

// ---------------- W prep: transpose + bf16 hi/lo split, once per scale ----------------
__global__ void prep_w_kernel(const float* __restrict__ W) {
    int si = blockIdx.x;
    for (int it = threadIdx.x; it < C_DIM * PB; it += blockDim.x) {
        int n = it / PB;
        int k = it - n * PB;
        unsigned short hi = 0, lo = 0;
        if (k < C_DIM) {
            float v = __ldg(&W[((size_t)si * C_DIM + k) * C_DIM + n]);
            __nv_bfloat16 h = __float2bfloat16_rn(v);
            float l = v - __bfloat162float(h);
            hi = __bfloat16_as_ushort(h);
            lo = __bfloat16_as_ushort(__float2bfloat16_rn(l));
        }
        g_Whi[si * C_DIM * PB + it] = hi;
        g_Wlo[si * C_DIM * PB + it] = lo;
    }
}

// ---------------- bucket assignment, ALL scales in one pass ----------------
// key < 2^30, scale packed in bits 30..31 -> one shared hash.
__global__ void assign_all_kernel(const int* __restrict__ indices) {
    int p = blockIdx.x * blockDim.x + threadIdx.x;
    if (p >= M_PTS) return;
    int4 v = ((const int4*)indices)[p];               // batch, x, y, z
    #pragma unroll
    for (int si = 0; si < S_NUM; si++) {
        int shift = si + 1;                            // scales 2,4,8,16
        unsigned int cx = ((unsigned int)v.y) >> shift;
        unsigned int cy = ((unsigned int)v.z) >> shift;
        unsigned int cz = ((unsigned int)v.w) >> shift;
        unsigned int key = (((unsigned int)v.x * 512u + cx) * 512u + cy) * 512u + cz;
        key |= (unsigned int)si << 30;

        ull_t desired = ((ull_t)key << 32) | (unsigned int)p;
        unsigned int slot = (key * 2654435761u) & HASH_MASK;
        int id;
        while (true) {
            ull_t prev = atomicCAS(&g_hash[slot], ~0ull, desired);
            if (prev == ~0ull) { id = p; break; }
            if ((unsigned int)(prev >> 32) == key) { id = (int)(unsigned int)prev; break; }
            slot = (slot + 1u) & HASH_MASK;
        }
        g_point_bucket[si * M_PTS + p] = id;
        atomicAdd(&g_bucket_count[si * M_PTS + id], 1);
    }
}

// ---------------- scatter-add feats into bucket sums for scale si ----------------
__global__ void accumulate_kernel(const float* __restrict__ feats, int si) {
    int t = blockIdx.x * blockDim.x + threadIdx.x;
    if (t >= M_PTS * 32) return;                       // 32 float4 groups per point
    int p = t >> 5;
    int cg = t & 31;
    int b = __ldg(&g_point_bucket[si * M_PTS + p]);
    if (__ldg(&g_bucket_count[si * M_PTS + b]) == 1) return;   // singleton: Os == 0
    float4 f = ((const float4*)feats)[t];
    float* dst = &g_bucket_sums[(size_t)b * C_DIM + cg * 4];
    atomicAdd(dst + 0, f.x);
    atomicAdd(dst + 1, f.y);
    atomicAdd(dst + 2, f.z);
    atomicAdd(dst + 3, f.w);
}

// ---------------- persistent HMMA GEMM: B resident, register BN accumulators ----------
__global__ void __launch_bounds__(256, 2)
gemm_tc_kernel(const float* __restrict__ feats, const float* __restrict__ bias,
               float* __restrict__ out, int si)
{
    extern __shared__ __align__(16) char smraw[];
    unsigned short* Ah = (unsigned short*)smraw;        // [TM][PA]
    unsigned short* Al = Ah + TM * PA;
    unsigned short* Bh = Al + TM * PA;                  // [128][PB]
    unsigned short* Bl = Bh + 128 * PB;

    __shared__ float s_bias[128];
    __shared__ float s_inv[TM];
    __shared__ int   s_bkt[TM];                         // bucket id, or -1 if singleton/oob

    int tid = threadIdx.x;
    int wid = tid >> 5;
    int lid = tid & 31;
    const int wm = wid & 3;        // M quadrant (16 rows)
    const int wn = wid >> 2;       // N half (64 cols)
    const int g  = lid >> 2;       // 0..7
    const int c2 = (lid & 3) * 2;  // 0,2,4,6

    if (tid < 128) s_bias[tid] = __ldg(&bias[si * C_DIM + tid]);

    // --- B tiles: copied ONCE per CTA ---
    {
        const uint4* srcH = (const uint4*)(g_Whi + (size_t)si * C_DIM * PB);
        const uint4* srcL = (const uint4*)(g_Wlo + (size_t)si * C_DIM * PB);
        uint4* dH = (uint4*)Bh;
        uint4* dL = (uint4*)Bl;
        const int nvec = C_DIM * PB * 2 / 16;          // 2176
        for (int it = tid; it < nvec; it += 256) {
            dH[it] = srcH[it];
            dL[it] = srcL[it];
        }
    }

    const uint32_t AhU = smem_u32(Ah), AlU = smem_u32(Al);
    const uint32_t BhU = smem_u32(Bh), BlU = smem_u32(Bl);
    const uint32_t aoff = (uint32_t)(wm * 16 + (lid & 15)) * (PA * 2) + ((lid >> 4) * 16);
    const uint32_t boff = (uint32_t)(wn * 64 + (lid & 7) + ((lid >> 4) * 8)) * (PB * 2)
                        + (((lid >> 3) & 1) * 16);

    const int* pb  = g_point_bucket + si * M_PTS;
    const int* pc  = g_bucket_count + si * M_PTS;
    const float4* s4 = (const float4*)g_bucket_sums;

    // register BN accumulators (per-thread columns wn*64 + j*8 + c2 {,+1})
    float bnS[16], bnQ[16];
    #pragma unroll
    for (int q = 0; q < 16; q++) { bnS[q] = 0.f; bnQ[q] = 0.f; }
    int fastRows = 0;

    for (int blk = blockIdx.x; blk < NBLOCKS; blk += gridDim.x) {
        int row0 = blk * TM;
        int rows = M_PTS - row0; if (rows > TM) rows = TM;

        int multi = 0;
        if (tid < TM) {
            int b = -1; float inv = 0.f;
            if (tid < rows) {
                b = __ldg(&pb[row0 + tid]);
                int c = __ldg(&pc[b]);
                if (c == 1) b = -1;                     // singleton: Os row == 0
                else { inv = 1.0f / (float)c; multi = 1; }
            }
            s_bkt[tid] = b; s_inv[tid] = inv;
        }
        // barrier: also protects smem (A tiles, meta) against previous iteration readers
        int nmulti = __syncthreads_count(multi);

        if (nmulti == 0) {
            // ---- fast path: every row singleton -> Os == 0 -> h = bias exactly ----
            const float4* b4 = (const float4*)s_bias;
            float4* o4 = (float4*)out;
            for (int i = tid; i < rows * 32; i += 256) {
                int r = i >> 5, cg = i & 31;
                o4[(size_t)(row0 + r) * 128 + si * 32 + cg] = b4[cg];
            }
            fastRows += rows;
            continue;
        }

        // --- A tile: Os = (f - mean)*f, truncation hi/lo split ---
        {
            const float4* f4 = (const float4*)feats;
            for (int it = tid; it < TM * 32; it += 256) {
                int r = it >> 5, cg = it & 31;
                ull_t hv = 0ull, lv = 0ull;
                int bkt = (r < rows) ? s_bkt[r] : -1;
                if (bkt >= 0) {
                    int p = row0 + r;
                    float4 f = f4[(size_t)p * 32 + cg];
                    float4 su = s4[(size_t)bkt * 32 + cg];
                    float inv = s_inv[r];
                    float o0 = (f.x - su.x * inv) * f.x;
                    float o1 = (f.y - su.y * inv) * f.y;
                    float o2 = (f.z - su.z * inv) * f.z;
                    float o3 = (f.w - su.w * inv) * f.w;
                    uint32_t u0 = __float_as_uint(o0), u1 = __float_as_uint(o1);
                    uint32_t u2 = __float_as_uint(o2), u3 = __float_as_uint(o3);
                    uint32_t h01 = __byte_perm(u0, u1, 0x7632);
                    uint32_t h23 = __byte_perm(u2, u3, 0x7632);
                    float l0 = o0 - __uint_as_float(u0 & 0xFFFF0000u);
                    float l1 = o1 - __uint_as_float(u1 & 0xFFFF0000u);
                    float l2 = o2 - __uint_as_float(u2 & 0xFFFF0000u);
                    float l3 = o3 - __uint_as_float(u3 & 0xFFFF0000u);
                    uint32_t lo01 = bf16x2_rn(l1, l0);
                    uint32_t lo23 = bf16x2_rn(l3, l2);
                    hv = (ull_t)h01 | ((ull_t)h23 << 32);
                    lv = (ull_t)lo01 | ((ull_t)lo23 << 32);
                }
                *(ull_t*)&Ah[r * PA + cg * 4] = hv;
                *(ull_t*)&Al[r * PA + cg * 4] = lv;
            }
        }
        __syncthreads();

        // --- mainloop: warp = 16(M) x 64(N), ldmatrix fragment loads ---
        float acc[8][4];
        #pragma unroll
        for (int j = 0; j < 8; j++)
            #pragma unroll
            for (int q = 0; q < 4; q++) acc[j][q] = 0.f;

        #pragma unroll
        for (int kc = 0; kc < 8; kc++) {
            uint32_t ah[4], al[4];
            LDSM_X4(ah[0], ah[1], ah[2], ah[3], AhU + aoff + kc * 32);
            LDSM_X4(al[0], al[1], al[2], al[3], AlU + aoff + kc * 32);
            #pragma unroll
            for (int jp = 0; jp < 4; jp++) {
                uint32_t bh[4], bl[4];
                uint32_t ba = boff + (uint32_t)jp * (16 * PB * 2) + kc * 32;
                LDSM_X4(bh[0], bh[1], bh[2], bh[3], BhU + ba);
                LDSM_X4(bl[0], bl[1], bl[2], bl[3], BlU + ba);
                mma16816(acc[2 * jp],     ah, bh[0], bh[1]);   // hi*hi
                mma16816(acc[2 * jp],     al, bh[0], bh[1]);   // lo*hi
                mma16816(acc[2 * jp],     ah, bl[0], bl[1]);   // hi*lo
                mma16816(acc[2 * jp + 1], ah, bh[2], bh[3]);
                mma16816(acc[2 * jp + 1], al, bh[2], bh[3]);
                mma16816(acc[2 * jp + 1], ah, bl[2], bl[3]);
            }
        }

        // --- epilogue: bias add, store h, BN partials into registers ---
        {
            int r0l = wm * 16 + g;                 // local row of c0/c1
            int r1l = r0l + 8;                     // local row of c2/c3
            bool v0 = r0l < rows, v1 = r1l < rows;
            #pragma unroll
            for (int j = 0; j < 8; j++) {
                int col = wn * 64 + j * 8 + c2;
                float b0 = s_bias[col], b1 = s_bias[col + 1];
                float h00 = v0 ? acc[j][0] + b0 : 0.f;
                float h01 = v0 ? acc[j][1] + b1 : 0.f;
                float h10 = v1 ? acc[j][2] + b0 : 0.f;
                float h11 = v1 ? acc[j][3] + b1 : 0.f;
                if (v0) {
                    float2* p = (float2*)&out[(size_t)(row0 + r0l) * (S_NUM * C_DIM)
                                              + si * C_DIM + col];
                    *p = make_float2(h00, h01);
                }
                if (v1) {
                    float2* p = (float2*)&out[(size_t)(row0 + r1l) * (S_NUM * C_DIM)
                                              + si * C_DIM + col];
                    *p = make_float2(h10, h11);
                }
                float s0 = h00 + h10, s1 = h01 + h11;
                float q0 = h00 * h00 + h10 * h10, q1 = h01 * h01 + h11 * h11;
                #pragma unroll
                for (int o = 4; o < 32; o <<= 1) {
                    s0 += __shfl_xor_sync(0xffffffffu, s0, o);
                    s1 += __shfl_xor_sync(0xffffffffu, s1, o);
                    q0 += __shfl_xor_sync(0xffffffffu, q0, o);
                    q1 += __shfl_xor_sync(0xffffffffu, q1, o);
                }
                // butterfly leaves every lane with this warp's 16-row column total
                bnS[2 * j]     += s0;  bnS[2 * j + 1] += s1;
                bnQ[2 * j]     += q0;  bnQ[2 * j + 1] += q1;
            }
        }
    }

    // --- flush BN accumulators once per CTA (lanes g==0, one pair per j) ---
    if (g == 0) {
        float fs = (wm == 0) ? (float)fastRows : 0.f;   // fast rows counted once per wn
        #pragma unroll
        for (int j = 0; j < 8; j++) {
            int col = wn * 64 + j * 8 + c2;
            float b0 = s_bias[col], b1 = s_bias[col + 1];
            atomicAdd(&g_ch_sum[si * C_DIM + col],       bnS[2 * j]     + fs * b0);
            atomicAdd(&g_ch_sumsq[si * C_DIM + col],     bnQ[2 * j]     + fs * b0 * b0);
            atomicAdd(&g_ch_sum[si * C_DIM + col + 1],   bnS[2 * j + 1] + fs * b1);
            atomicAdd(&g_ch_sumsq[si * C_DIM + col + 1], bnQ[2 * j + 1] + fs * b1 * b1);
        }
    }
}

// ---------------- BN finalize: per (scale, channel) affine ----------------
__global__ void finalize_kernel(const float* __restrict__ gamma,
                                const float* __restrict__ beta) {
    int i = blockIdx.x * blockDim.x + threadIdx.x;
    if (i >= S_NUM * C_DIM) return;
    const float invM = 1.0f / (float)M_PTS;
    float mu  = g_ch_sum[i] * invM;
    float var = g_ch_sumsq[i] * invM - mu * mu;
    float rstd = rsqrtf(var + 1e-5f);
    float a = rstd * __ldg(&gamma[i]);
    g_bn_scale[i] = a;
    g_bn_shift[i] = __ldg(&beta[i]) - mu * a;
}

// ---------------- BN apply + LeakyReLU over whole output ----------------
__global__ void bn_apply_kernel(float* __restrict__ out) {
    long long i = (long long)blockIdx.x * blockDim.x + threadIdx.x;
    if (i >= (long long)M_PTS * 128) return;           // float4 granularity
    int sc4 = (int)(i & 127);                           // float4 index into [512]
    float4 h = ((float4*)out)[i];
    float4 a = ((const float4*)g_bn_scale)[sc4];
    float4 b = ((const float4*)g_bn_shift)[sc4];
    float x0 = h.x * a.x + b.x;
    float x1 = h.y * a.y + b.y;
    float x2 = h.z * a.z + b.z;
    float x3 = h.w * a.w + b.w;
    x0 = x0 > 0.f ? x0 : 0.01f * x0;
    x1 = x1 > 0.f ? x1 : 0.01f * x1;
    x2 = x2 > 0.f ? x2 : 0.01f * x2;
    x3 = x3 > 0.f ? x3 : 0.01f * x3;
    ((float4*)out)[i] = make_float4(x0, x1, x2, x3);
}

// ---------------- launch ----------------
extern "C" void kernel_launch(void* const* d_in, const int* in_sizes, int n_in,
                              void* d_out, int out_size) {
    const float* feats   = (const float*)d_in[0];
    const int*   indices = (const int*)d_in[1];
    const float* W       = (const float*)d_in[2];
    const float* b       = (const float*)d_in[3];
    const float* gamma   = (const float*)d_in[4];
    const float* beta    = (const float*)d_in[5];
    float* out = (float*)d_out;

    const int gemm_smem = (2 * TM * PA + 2 * 128 * PB) * 2;   // 104448 B
    cudaFuncSetAttribute(gemm_tc_kernel,
                         cudaFuncAttributeMaxDynamicSharedMemorySize, gemm_smem);
    int gemm_grid = GEMM_GRID < NBLOCKS ? GEMM_GRID : NBLOCKS;

    clear_all_kernel<<<(int)((HASH_SIZE + 255) / 256), 256>>>();
    prep_w_kernel<<<S_NUM, 256>>>(W);
    assign_all_kernel<<<(M_PTS + 255) / 256, 256>>>(indices);

    for (int si = 0; si < S_NUM; si++) {
        clear_sums_kernel<<<(M_PTS * 32 + 255) / 256, 256>>>(si);
        accumulate_kernel<<<(M_PTS * 32 + 255) / 256, 256>>>(feats, si);
        gemm_tc_kernel<<<gemm_grid, 256, gemm_smem>>>(feats, b, out, si);
    }

    finalize_kernel<<<1, 512>>>(gamma, beta);
    bn_apply_kernel<<<(int)(((long long)M_PTS * 128 + 255) / 256), 256>>>(out);
}